// round 2
// baseline (speedup 1.0000x reference)
#include <cuda_runtime.h>
#include <cstdint>

// 2D Haar DWT, one level.
// Input:  x  (16,1,2048,2048) fp32
// Output: [ll | lh | hl | hh], each (16,1,1024,1024) fp32, concatenated.
//
// Thread mapping: thread t handles batch b, output row i, and FOUR output
// columns [4*q .. 4*q+3]. It loads two float4 from each of input rows 2i and
// 2i+1 (8 input columns), and writes one float4 per band (streaming stores).

static __device__ __forceinline__ float safef(float v) {
    return isfinite(v) ? v : 0.0f;
}

static __device__ __forceinline__ void haar2(
    float a, float b, float c, float d,
    float& ll, float& lh, float& hl, float& hh)
{
    a = safef(a); b = safef(b); c = safef(c); d = safef(d);
    const float h = 0.5f;
    ll = h * ( a + b + c + d);
    lh = h * (-a + b - c + d);
    hl = h * (-a - b + c + d);
    hh = h * ( a - b - c + d);
}

__global__ void __launch_bounds__(256) dwt2d_haar_kernel(
    const float* __restrict__ x, float* __restrict__ out)
{
    constexpr int W  = 2048;     // input width
    constexpr int Wo = 1024;     // output width
    constexpr int Ho = 1024;     // output height
    constexpr int QP = Wo / 4;   // 256 quad-groups per output row
    const long long NB = 16LL * Ho * Wo; // elements per band

    long long t = (long long)blockIdx.x * blockDim.x + threadIdx.x;
    // t in [0, 16*1024*256)
    int q = (int)(t & (QP - 1));         // quad index, 0..255
    long long rest = t >> 8;
    int i  = (int)(rest & (Ho - 1));     // output row, 0..1023
    long long b = rest >> 10;            // batch, 0..15

    const float4* row0 = reinterpret_cast<const float4*>(
        x + (b * W + 2LL * i) * W);
    const float4* row1 = reinterpret_cast<const float4*>(
        x + (b * W + 2LL * i + 1) * W);

    // 8 input columns starting at 8*q -> float4 indices 2q, 2q+1
    float4 r0a = __ldcs(&row0[2 * q]);
    float4 r0b = __ldcs(&row0[2 * q + 1]);
    float4 r1a = __ldcs(&row1[2 * q]);
    float4 r1b = __ldcs(&row1[2 * q + 1]);

    float4 ll, lh, hl, hh;
    haar2(r0a.x, r0a.y, r1a.x, r1a.y, ll.x, lh.x, hl.x, hh.x);
    haar2(r0a.z, r0a.w, r1a.z, r1a.w, ll.y, lh.y, hl.y, hh.y);
    haar2(r0b.x, r0b.y, r1b.x, r1b.y, ll.z, lh.z, hl.z, hh.z);
    haar2(r0b.z, r0b.w, r1b.z, r1b.w, ll.w, lh.w, hl.w, hh.w);

    long long o = (b * Ho + i) * Wo + 4LL * q; // element offset within a band
    float4* po = reinterpret_cast<float4*>(out);
    long long o4 = o >> 2;            // float4 offset
    long long nb4 = NB >> 2;          // float4 elements per band

    __stcs(&po[o4],           ll);
    __stcs(&po[o4 + nb4],     lh);
    __stcs(&po[o4 + 2 * nb4], hl);
    __stcs(&po[o4 + 3 * nb4], hh);
}

extern "C" void kernel_launch(void* const* d_in, const int* in_sizes, int n_in,
                              void* d_out, int out_size)
{
    const float* x = (const float*)d_in[0];
    float* out = (float*)d_out;

    const long long total_threads = 16LL * 1024 * 256; // 4,194,304
    const int block = 256;
    const long long grid = total_threads / block;       // 16384

    dwt2d_haar_kernel<<<(unsigned)grid, block>>>(x, out);
}

// round 3
// speedup vs baseline: 1.0020x; 1.0020x over previous
#include <cuda_runtime.h>
#include <cstdint>

// 2D Haar DWT, one level.
// Input:  x  (16,1,2048,2048) fp32
// Output: [ll | lh | hl | hh], each (16,1,1024,1024) fp32, concatenated.
//
// Thread mapping: thread t handles batch b, output row i, and FOUR output
// columns [4*q .. 4*q+3]. It loads two float4 from each of input rows 2i and
// 2i+1 (8 input columns), and writes one float4 per band (streaming stores).

static __device__ __forceinline__ float safef(float v) {
    return isfinite(v) ? v : 0.0f;
}

static __device__ __forceinline__ void haar2(
    float a, float b, float c, float d,
    float& ll, float& lh, float& hl, float& hh)
{
    a = safef(a); b = safef(b); c = safef(c); d = safef(d);
    const float h = 0.5f;
    ll = h * ( a + b + c + d);
    lh = h * (-a + b - c + d);
    hl = h * (-a - b + c + d);
    hh = h * ( a - b - c + d);
}

__global__ void __launch_bounds__(256) dwt2d_haar_kernel(
    const float* __restrict__ x, float* __restrict__ out)
{
    constexpr int W  = 2048;     // input width
    constexpr int Wo = 1024;     // output width
    constexpr int Ho = 1024;     // output height
    constexpr int QP = Wo / 4;   // 256 quad-groups per output row
    const long long NB = 16LL * Ho * Wo; // elements per band

    long long t = (long long)blockIdx.x * blockDim.x + threadIdx.x;
    // t in [0, 16*1024*256)
    int q = (int)(t & (QP - 1));         // quad index, 0..255
    long long rest = t >> 8;
    int i  = (int)(rest & (Ho - 1));     // output row, 0..1023
    long long b = rest >> 10;            // batch, 0..15

    const float4* row0 = reinterpret_cast<const float4*>(
        x + (b * W + 2LL * i) * W);
    const float4* row1 = reinterpret_cast<const float4*>(
        x + (b * W + 2LL * i + 1) * W);

    // 8 input columns starting at 8*q -> float4 indices 2q, 2q+1
    float4 r0a = __ldcs(&row0[2 * q]);
    float4 r0b = __ldcs(&row0[2 * q + 1]);
    float4 r1a = __ldcs(&row1[2 * q]);
    float4 r1b = __ldcs(&row1[2 * q + 1]);

    float4 ll, lh, hl, hh;
    haar2(r0a.x, r0a.y, r1a.x, r1a.y, ll.x, lh.x, hl.x, hh.x);
    haar2(r0a.z, r0a.w, r1a.z, r1a.w, ll.y, lh.y, hl.y, hh.y);
    haar2(r0b.x, r0b.y, r1b.x, r1b.y, ll.z, lh.z, hl.z, hh.z);
    haar2(r0b.z, r0b.w, r1b.z, r1b.w, ll.w, lh.w, hl.w, hh.w);

    long long o = (b * Ho + i) * Wo + 4LL * q; // element offset within a band
    float4* po = reinterpret_cast<float4*>(out);
    long long o4 = o >> 2;            // float4 offset
    long long nb4 = NB >> 2;          // float4 elements per band

    __stcs(&po[o4],           ll);
    __stcs(&po[o4 + nb4],     lh);
    __stcs(&po[o4 + 2 * nb4], hl);
    __stcs(&po[o4 + 3 * nb4], hh);
}

extern "C" void kernel_launch(void* const* d_in, const int* in_sizes, int n_in,
                              void* d_out, int out_size)
{
    const float* x = (const float*)d_in[0];
    float* out = (float*)d_out;

    const long long total_threads = 16LL * 1024 * 256; // 4,194,304
    const int block = 256;
    const long long grid = total_threads / block;       // 16384

    dwt2d_haar_kernel<<<(unsigned)grid, block>>>(x, out);
}